// round 9
// baseline (speedup 1.0000x reference)
#include <cuda_runtime.h>
#include <math.h>

#define B_  2
#define S_  2048
#define D_  1024
#define H_  16
#define HD_ 64

// Scratch (allocation-free rule: device globals)
__device__ float g_q[B_ * S_ * D_];
__device__ float g_k[B_ * S_ * D_];
__device__ float g_v[B_ * S_ * D_];
__device__ float g_att[B_ * S_ * D_];
__device__ float g_cos[S_ * (HD_ / 2)];
__device__ float g_sin[S_ * (HD_ / 2)];

// ---------------------------------------------------------------------------
// RoPE tables. Reference computes angles in float64 (numpy promotes), so do we.
// ---------------------------------------------------------------------------
__global__ void rope_init_kernel() {
    int idx = blockIdx.x * blockDim.x + threadIdx.x;
    if (idx < S_ * 32) {
        int s = idx >> 5, p = idx & 31;
        double inv = pow(10000.0, -((double)(2 * p)) / 64.0);
        double ang = (double)s * inv;
        g_cos[idx] = (float)cos(ang);
        g_sin[idx] = (float)sin(ang);
    }
}

// ---------------------------------------------------------------------------
// SGEMM: C[m,n] = sum_k A[m,k] * W[n,k] + bias[n]   (NT, both K-contiguous)
// BM=BN=128, BK=16, 256 threads, 8x8 per thread (2x2 blocks of 4x4).
// mode: 0 -> C=g_q (RoPE), 1 -> C=g_k (RoPE), 2 -> C=g_v, 3 -> A=g_att, C=Cext
// ---------------------------------------------------------------------------
__global__ __launch_bounds__(256, 2) void gemm_kernel(
    const float* __restrict__ Aext, const float* __restrict__ W,
    const float* __restrict__ bias, float* __restrict__ Cext, int mode)
{
    __shared__ float As[16][132];
    __shared__ float Bs[16][132];

    const float* A = (mode == 3) ? g_att : Aext;
    float* C = (mode == 0) ? g_q : (mode == 1) ? g_k : (mode == 2) ? g_v : Cext;
    const bool rope = (mode <= 1);

    const int m0 = blockIdx.y * 128;
    const int n0 = blockIdx.x * 128;
    const int tid = threadIdx.x;
    const int tx = tid & 15, ty = tid >> 4;
    const int lrow = tid >> 2;          // 0..63
    const int lk   = (tid & 3) << 2;    // 0,4,8,12

    float acc[8][8];
#pragma unroll
    for (int i = 0; i < 8; i++)
#pragma unroll
        for (int j = 0; j < 8; j++) acc[i][j] = 0.0f;

    for (int k0 = 0; k0 < D_; k0 += 16) {
#pragma unroll
        for (int p = 0; p < 2; p++) {
            const int r = lrow + p * 64;
            float4 av = *(const float4*)(A + (m0 + r) * D_ + k0 + lk);
            As[lk + 0][r] = av.x; As[lk + 1][r] = av.y;
            As[lk + 2][r] = av.z; As[lk + 3][r] = av.w;
            float4 wv = *(const float4*)(W + (n0 + r) * D_ + k0 + lk);
            Bs[lk + 0][r] = wv.x; Bs[lk + 1][r] = wv.y;
            Bs[lk + 2][r] = wv.z; Bs[lk + 3][r] = wv.w;
        }
        __syncthreads();
#pragma unroll
        for (int kk = 0; kk < 16; kk++) {
            float a[8], b[8];
            *(float4*)&a[0] = *(const float4*)&As[kk][ty * 4];
            *(float4*)&a[4] = *(const float4*)&As[kk][64 + ty * 4];
            *(float4*)&b[0] = *(const float4*)&Bs[kk][tx * 4];
            *(float4*)&b[4] = *(const float4*)&Bs[kk][64 + tx * 4];
#pragma unroll
            for (int i = 0; i < 8; i++)
#pragma unroll
                for (int j = 0; j < 8; j++)
                    acc[i][j] = fmaf(a[i], b[j], acc[i][j]);
        }
        __syncthreads();
    }

    // Epilogue: bias (+ optional RoPE), vectorized float4 stores.
#pragma unroll
    for (int rb = 0; rb < 2; rb++)
#pragma unroll
        for (int i = 0; i < 4; i++) {
            const int m = m0 + rb * 64 + ty * 4 + i;
            const int s = m & (S_ - 1);
#pragma unroll
            for (int cb = 0; cb < 2; cb++) {
                const int n = n0 + cb * 64 + tx * 4;
                float4 bsv = *(const float4*)(bias + n);
                float4 v;
                v.x = acc[rb * 4 + i][cb * 4 + 0] + bsv.x;
                v.y = acc[rb * 4 + i][cb * 4 + 1] + bsv.y;
                v.z = acc[rb * 4 + i][cb * 4 + 2] + bsv.z;
                v.w = acc[rb * 4 + i][cb * 4 + 3] + bsv.w;
                if (rope) {
                    const int p0 = (n & 63) >> 1;       // even pair index
                    const float c0 = g_cos[s * 32 + p0],     s0 = g_sin[s * 32 + p0];
                    const float c1 = g_cos[s * 32 + p0 + 1], s1 = g_sin[s * 32 + p0 + 1];
                    float o0 = v.x * c0 - v.y * s0;
                    float o1 = v.x * s0 + v.y * c0;
                    float o2 = v.z * c1 - v.w * s1;
                    float o3 = v.z * s1 + v.w * c1;
                    v = make_float4(o0, o1, o2, o3);
                }
                *(float4*)(C + m * D_ + n) = v;
            }
        }
}

// ---------------------------------------------------------------------------
// Flash attention, fp32. CTA = (64-row tile, head, batch). 256 thr (16x16).
// Smem: Qs[d][r] (transposed), KPs = K[d][c] then reused as P[r][c], Vs[c][d].
// Exactly 3 * 64*64 * 4B = 48 KB static shared.
// ---------------------------------------------------------------------------
__global__ __launch_bounds__(256) void attn_kernel(const int* __restrict__ eff)
{
    __shared__ float Qs[64 * 64];
    __shared__ float KPs[64 * 64];
    __shared__ float Vs[64 * 64];

    const int m0 = blockIdx.x * 64;
    const int h  = blockIdx.y;
    const int b  = blockIdx.z;
    const int kvlim = S_ - eff[b];      // keys with col >= kvlim are pad-masked

    const int tid = threadIdx.x;
    const int tx = tid & 15, ty = tid >> 4;

    const float* Qg = g_q + b * S_ * D_ + h * 64;
    const float* Kg = g_k + b * S_ * D_ + h * 64;
    const float* Vg = g_v + b * S_ * D_ + h * 64;

    // Load Q tile transposed: Qs[d][r]
#pragma unroll
    for (int it = 0; it < 16; it++) {
        const int idx = tid + it * 256;
        const int r = idx >> 6, d = idx & 63;
        Qs[d * 64 + r] = Qg[(m0 + r) * D_ + d];
    }

    float m_i[4], l_i[4], O[4][4];
#pragma unroll
    for (int i = 0; i < 4; i++) {
        m_i[i] = -1e30f; l_i[i] = 0.0f;
#pragma unroll
        for (int j = 0; j < 4; j++) O[i][j] = 0.0f;
    }

    const int nt = min(m0 + 64, kvlim);  // >= 1025 always (eff < 1024)
    for (int c0 = 0; c0 < nt; c0 += 64) {
        __syncthreads();  // prior PV reads done (also orders Q load, 1st iter)
#pragma unroll
        for (int it = 0; it < 16; it++) {
            const int idx = tid + it * 256;
            const int c = idx >> 6, d = idx & 63;
            KPs[d * 64 + c] = Kg[(c0 + c) * D_ + d];
            Vs[c * 64 + d]  = Vg[(c0 + c) * D_ + d];
        }
        __syncthreads();

        // Scores: S = Q K^T (uniform-row float4 smem reads -> conflict-free)
        float sc[4][4];
#pragma unroll
        for (int i = 0; i < 4; i++)
#pragma unroll
            for (int j = 0; j < 4; j++) sc[i][j] = 0.0f;
#pragma unroll
        for (int d = 0; d < 64; d++) {
            const float4 q4 = *(const float4*)&Qs[d * 64 + ty * 4];
            const float4 k4 = *(const float4*)&KPs[d * 64 + tx * 4];
            const float qa[4] = {q4.x, q4.y, q4.z, q4.w};
            const float kb[4] = {k4.x, k4.y, k4.z, k4.w};
#pragma unroll
            for (int i = 0; i < 4; i++)
#pragma unroll
                for (int j = 0; j < 4; j++)
                    sc[i][j] = fmaf(qa[i], kb[j], sc[i][j]);
        }

        // Scale + causal/pad mask
#pragma unroll
        for (int i = 0; i < 4; i++) {
            const int r = m0 + ty * 4 + i;
#pragma unroll
            for (int j = 0; j < 4; j++) {
                const int c = c0 + tx * 4 + j;
                sc[i][j] = (c <= r && c < kvlim) ? sc[i][j] * 0.125f : -1e30f;
            }
        }

        // Online softmax (row groups = 16 lanes sharing ty)
        float p[4][4];
#pragma unroll
        for (int i = 0; i < 4; i++) {
            float rm = fmaxf(fmaxf(sc[i][0], sc[i][1]), fmaxf(sc[i][2], sc[i][3]));
#pragma unroll
            for (int o = 8; o >= 1; o >>= 1)
                rm = fmaxf(rm, __shfl_xor_sync(0xffffffffu, rm, o, 16));
            const float mn = fmaxf(m_i[i], rm);
            const float alpha = __expf(m_i[i] - mn);
            m_i[i] = mn;
            float rs = 0.0f;
#pragma unroll
            for (int j = 0; j < 4; j++) {
                p[i][j] = __expf(sc[i][j] - mn);
                rs += p[i][j];
            }
#pragma unroll
            for (int o = 8; o >= 1; o >>= 1)
                rs += __shfl_xor_sync(0xffffffffu, rs, o, 16);
            l_i[i] = l_i[i] * alpha + rs;
#pragma unroll
            for (int j = 0; j < 4; j++) O[i][j] *= alpha;
        }

        __syncthreads();  // everyone done reading K from KPs
#pragma unroll
        for (int i = 0; i < 4; i++)
            *(float4*)&KPs[(ty * 4 + i) * 64 + tx * 4] =
                make_float4(p[i][0], p[i][1], p[i][2], p[i][3]);
        __syncthreads();

        // O += P @ V
#pragma unroll
        for (int c = 0; c < 64; c++) {
            const float4 v4 = *(const float4*)&Vs[c * 64 + tx * 4];
#pragma unroll
            for (int i = 0; i < 4; i++) {
                const float pi = KPs[(ty * 4 + i) * 64 + c];
                O[i][0] = fmaf(pi, v4.x, O[i][0]);
                O[i][1] = fmaf(pi, v4.y, O[i][1]);
                O[i][2] = fmaf(pi, v4.z, O[i][2]);
                O[i][3] = fmaf(pi, v4.w, O[i][3]);
            }
        }
    }

    // Normalize + store
#pragma unroll
    for (int i = 0; i < 4; i++) {
        const float inv = 1.0f / l_i[i];
        const float4 o4 = make_float4(O[i][0] * inv, O[i][1] * inv,
                                      O[i][2] * inv, O[i][3] * inv);
        *(float4*)&g_att[(b * S_ + m0 + ty * 4 + i) * D_ + h * 64 + tx * 4] = o4;
    }
}

// ---------------------------------------------------------------------------
extern "C" void kernel_launch(void* const* d_in, const int* in_sizes, int n_in,
                              void* d_out, int out_size)
{
    (void)in_sizes; (void)n_in; (void)out_size;
    const float* x  = (const float*)d_in[0];
    const int*   ef = (const int*)  d_in[1];
    const float* Wq = (const float*)d_in[2];
    const float* bq = (const float*)d_in[3];
    const float* Wk = (const float*)d_in[4];
    const float* bk = (const float*)d_in[5];
    const float* Wv = (const float*)d_in[6];
    const float* bv = (const float*)d_in[7];
    const float* Wo = (const float*)d_in[8];
    const float* bo = (const float*)d_in[9];
    float* out = (float*)d_out;

    rope_init_kernel<<<(S_ * 32 + 255) / 256, 256>>>();

    const dim3 gg(D_ / 128, (B_ * S_) / 128);   // 8 x 32
    gemm_kernel<<<gg, 256>>>(x, Wq, bq, nullptr, 0);  // Q + RoPE
    gemm_kernel<<<gg, 256>>>(x, Wk, bk, nullptr, 1);  // K + RoPE
    gemm_kernel<<<gg, 256>>>(x, Wv, bv, nullptr, 2);  // V

    attn_kernel<<<dim3(S_ / 64, H_, B_), 256>>>(ef);

    gemm_kernel<<<gg, 256>>>(nullptr, Wo, bo, out, 3);  // out proj
}